// round 14
// baseline (speedup 1.0000x reference)
#include <cuda_runtime.h>
#include <math.h>
#include <stdint.h>

#define BATCH   8
#define SEQ     200
#define NNODES  512
#define HID     64
#define NEDGES  2048
#define ALPHA   0.2f
#define NEGBIG  -9.0e15f
#define CONV_BGRID 256

// ---------------- scratch (device globals, no allocation) ----------------
__device__ float g_Wh1[BATCH * NNODES * HID];
__device__ float g_Wh2[BATCH * NNODES * HID];
__device__ float g_h2[BATCH * NNODES * HID];
__device__ float g_f1a[BATCH * NNODES];
__device__ float g_f2a[BATCH * NNODES];
__device__ float g_f1b[BATCH * NNODES];
__device__ float g_f2b[BATCH * NNODES];
__device__ uint4 g_w2t[160 * 72 / 4];     // tf32, [r][n] transposed, stride 72

// ---------------- tf32 helpers ----------------
__device__ __forceinline__ uint32_t f2tf32(float f) {
    uint32_t r;
    asm("cvt.rna.tf32.f32 %0, %1;" : "=r"(r) : "f"(f));
    return r;
}
__device__ __forceinline__ void mma_tf32(float* c,
                                         uint32_t a0, uint32_t a1, uint32_t a2, uint32_t a3,
                                         uint32_t b0, uint32_t b1) {
    asm volatile(
        "mma.sync.aligned.m16n8k8.row.col.f32.tf32.tf32.f32 "
        "{%0,%1,%2,%3}, {%4,%5,%6,%7}, {%8,%9}, {%0,%1,%2,%3};"
        : "+f"(c[0]), "+f"(c[1]), "+f"(c[2]), "+f"(c[3])
        : "r"(a0), "r"(a1), "r"(a2), "r"(a3), "r"(b0), "r"(b1));
}

// ---------------- setup: pre-convert conv2 weights ----------
__global__ void pack_w2_kernel(const float* __restrict__ w2) {
    int i = blockIdx.x * blockDim.x + threadIdx.x;
    if (i >= 160 * 72) return;
    int r = i / 72, nn = i - r * 72;
    uint32_t v = (nn < 64) ? f2tf32(w2[nn * 160 + r]) : 0u;
    ((uint32_t*)g_w2t)[r * 72 + nn] = v;
}

// ---------------- Stage A: per-batch conv + fused gat_pre1 ----------
#define H1W   264
#define W2P   72
#define S_H1_OFF  0
#define S_W2_OFF  (32 * H1W)                  // 8448
#define S_IN_OFF  (S_W2_OFF + 160 * W2P)      // 19968
#define S_W1_OFF  (S_IN_OFF + 2 * 208)        // 20384
#define S_RED_OFF (S_W1_OFF + 320)            // 20704
#define S_H0_OFF  (S_RED_OFF + 512)           // 21216
#define S_PT_OFF  (S_H0_OFF + 64)             // 21280
#define CONV_SMEM_FLOATS (S_PT_OFF + 256)     // 21536
#define CONV_SMEM_BYTES  (CONV_SMEM_FLOATS * 4)

__global__ void __launch_bounds__(256, 2)
conv_fused_kernel(const float* __restrict__ x,
                  const float* __restrict__ w1, const float* __restrict__ b1,
                  const float* __restrict__ b2,
                  const float* __restrict__ W1, const float* __restrict__ a1,
                  float* __restrict__ Wh, float* __restrict__ f1, float* __restrict__ f2,
                  int batch)
{
    extern __shared__ float sm[];
    float* s_h1  = sm + S_H1_OFF;
    float* s_w2  = sm + S_W2_OFF;
    float* s_in  = sm + S_IN_OFF;
    float* s_w1  = sm + S_W1_OFF;
    float* s_red = sm + S_RED_OFF;
    float* s_h0  = sm + S_H0_OFF;
    float* s_pt  = sm + S_PT_OFF;

    const int tid = threadIdx.x;

    // one-time per block: weights + input pads
    for (int i = tid; i < 320; i += 256) s_w1[i] = w1[i];
    {
        uint4* dst = (uint4*)s_w2;
        for (int i = tid; i < 2880; i += 256) dst[i] = g_w2t[i];
    }
    if (tid < 16) {
        int c = tid >> 3, q = tid & 7;
        int idx = (q < 2) ? q : (200 + q);     // 0,1,202..207
        s_in[c * 208 + idx] = 0.f;
    }

    const int warp = tid >> 5;
    const int lane = tid & 31;
    const int g    = lane >> 2;
    const int t4   = lane & 3;

    const int sA = tid >> 1,          cA = tid & 1;
    const int sB = (tid + 256) >> 1,  cB = tid & 1;
    const bool has2 = (tid < 144);

    const float* xbase = x + (size_t)batch * SEQ * (NNODES * 2);

    // prefetch first node's input
    float xv0 = 0.f, xv1 = 0.f;
    {
        const float* xb = xbase + 2 * blockIdx.x;
        xv0 = xb[(size_t)sA * (NNODES * 2) + cA];
        if (has2) xv1 = xb[(size_t)sB * (NNODES * 2) + cB];
    }

    for (int n = blockIdx.x; n < NNODES; n += CONV_BGRID) {
        const int bn = batch * NNODES + n;

        s_in[cA * 208 + 2 + sA] = xv0;
        if (has2) s_in[cB * 208 + 2 + sB] = xv1;
        __syncthreads();

        // conv1 + relu -> tf32 h1 (sliding window)
        {
            const int ic = tid >> 3;
            const int j  = tid & 7;
            const int sj = 25 * j;
            const float b1i = b1[ic];
            const float* w  = s_w1 + ic * 10;
            uint32_t* h1u = (uint32_t*)(s_h1 + ic * H1W);

            float a0[29], a1v[29];
            const float* i0 = s_in + sj;
            const float* i1 = s_in + 208 + sj;
#pragma unroll
            for (int q = 0; q < 29; q++) { a0[q] = i0[q]; a1v[q] = i1[q]; }

#pragma unroll
            for (int q = 0; q < 25; q++) {
                float acc = b1i;
#pragma unroll
                for (int k = 0; k < 5; k++)
                    acc = fmaf(w[k], a0[q + k], fmaf(w[5 + k], a1v[q + k], acc));
                h1u[2 + sj + q] = f2tf32(fmaxf(acc, 0.f));
            }
            if (j == 0) { h1u[0] = 0u; h1u[1] = 0u; }
            if (j == 7) {
#pragma unroll
                for (int q = 0; q < 10; q++) h1u[202 + q] = 0u;
            }
        }
        __syncthreads();

        // prefetch NEXT node's input (hidden under GEMM)
        {
            const int nn = n + CONV_BGRID;
            if (nn < NNODES) {
                const float* xb = xbase + 2 * nn;
                xv0 = xb[(size_t)sA * (NNODES * 2) + cA];
                if (has2) xv1 = xb[(size_t)sB * (NNODES * 2) + cB];
            }
        }

        // -------- tensor-core GEMM --------
        const uint32_t* h1u = (const uint32_t*)s_h1;
        const uint32_t* w2u = (const uint32_t*)s_w2;

        float c[2][8][4];
#pragma unroll
        for (int mt = 0; mt < 2; mt++)
#pragma unroll
            for (int nt = 0; nt < 8; nt++)
#pragma unroll
                for (int q = 0; q < 4; q++) c[mt][nt][q] = 0.f;

#pragma unroll 2
        for (int kc = 0; kc < 20; kc++) {
            const int r0 = kc * 8 + t4;
            const int r1 = r0 + 4;
            const int ic0 = r0 / 5, k0 = r0 - ic0 * 5;
            const int ic1 = r1 / 5, k1 = r1 - ic1 * 5;

            uint32_t bb0[8], bb1[8];
#pragma unroll
            for (int nt = 0; nt < 8; nt++) {
                bb0[nt] = w2u[r0 * W2P + nt * 8 + g];
                bb1[nt] = w2u[r1 * W2P + nt * 8 + g];
            }

            const int ao0 = ic0 * H1W + k0;
            const int ao1 = ic1 * H1W + k1;
#pragma unroll
            for (int mt = 0; mt < 2; mt++) {
                const int tile = warp + 8 * mt;
                if (tile >= 13) continue;
                const int sb = tile * 16 + g;
                uint32_t a0 = h1u[ao0 + sb];
                uint32_t a1 = h1u[ao0 + sb + 8];
                uint32_t a2 = h1u[ao1 + sb];
                uint32_t a3 = h1u[ao1 + sb + 8];
#pragma unroll
                for (int nt = 0; nt < 8; nt++)
                    mma_tf32(c[mt][nt], a0, a1, a2, a3, bb0[nt], bb1[nt]);
            }
        }

        // -------- epilogue: bias + relu + masked sum --------
#pragma unroll
        for (int nt = 0; nt < 8; nt++) {
            const int n0 = nt * 8 + 2 * t4;
            const float bias0 = b2[n0], bias1 = b2[n0 + 1];
            float sm0 = 0.f, sm1 = 0.f;
#pragma unroll
            for (int mt = 0; mt < 2; mt++) {
                const int tile = warp + 8 * mt;
                if (tile >= 13) continue;
                const int rA = tile * 16 + g;
                const int rB = rA + 8;
                if (rA < 200) {
                    sm0 += fmaxf(c[mt][nt][0] + bias0, 0.f);
                    sm1 += fmaxf(c[mt][nt][1] + bias1, 0.f);
                }
                if (rB < 200) {
                    sm0 += fmaxf(c[mt][nt][2] + bias0, 0.f);
                    sm1 += fmaxf(c[mt][nt][3] + bias1, 0.f);
                }
            }
#pragma unroll
            for (int off = 16; off >= 4; off >>= 1) {
                sm0 += __shfl_down_sync(0xffffffffu, sm0, off);
                sm1 += __shfl_down_sync(0xffffffffu, sm1, off);
            }
            if (lane < 4) {
                s_red[warp * 64 + nt * 8 + 2 * lane]     = sm0;
                s_red[warp * 64 + nt * 8 + 2 * lane + 1] = sm1;
            }
        }
        __syncthreads();

        if (tid < 64) {
            float t = 0.f;
#pragma unroll
            for (int w = 0; w < 8; w++) t += s_red[w * 64 + tid];
            s_h0[tid] = t * (1.f / 200.f);
        }
        __syncthreads();

        // -------- fused gat_pre1 --------
        {
            const int kq = tid >> 6;
            const int d  = tid & 63;
            float acc = 0.f;
#pragma unroll
            for (int i = 0; i < 16; i++) {
                int k = kq * 16 + i;
                acc = fmaf(s_h0[k], __ldg(W1 + k * 64 + d), acc);
            }
            s_pt[kq * 64 + d] = acc;
        }
        __syncthreads();

        if (tid < 64) {
            float wh = s_pt[tid] + s_pt[64 + tid] + s_pt[128 + tid] + s_pt[192 + tid];
            Wh[(size_t)bn * 64 + tid] = wh;
            float v1 = wh * __ldg(a1 + tid);
            float v2 = wh * __ldg(a1 + 64 + tid);
#pragma unroll
            for (int o = 16; o; o >>= 1) {
                v1 += __shfl_down_sync(0xffffffffu, v1, o);
                v2 += __shfl_down_sync(0xffffffffu, v2, o);
            }
            if ((tid & 31) == 0) {
                s_pt[(tid >> 5) * 2]     = v1;
                s_pt[(tid >> 5) * 2 + 1] = v2;
            }
        }
        __syncthreads();
        if (tid == 0) {
            f1[bn] = s_pt[0] + s_pt[2];
            f2[bn] = s_pt[1] + s_pt[3];
        }
        __syncthreads();
    }
}

// ---------------- attention smem layout (dynamic, R9 shapes) ----
#define A_SP   0
#define A_SWH  8192
#define A_F2   12416
#define A_HL   12928
#define A_SUM  13952
#define ATT_SMEM_FLOATS 13968
#define ATT_SMEM_BYTES  (ATT_SMEM_FLOATS * 4)

__device__ __forceinline__ void att_softmax_phase(
    float* sp, float* s_f2, float* ssum,
    const float* __restrict__ f1, const float* __restrict__ f2,
    const int* __restrict__ adj, int b, int i0, int tid)
{
    const int w  = tid >> 5;
    const int ln = tid & 31;

    for (int i = tid; i < 512; i += 256) s_f2[i] = f2[b * NNODES + i];
    __syncthreads();

#pragma unroll
    for (int rr = 0; rr < 2; rr++) {
        const int r = w * 2 + rr;
        const int i = i0 + r;
        const float f1i = f1[b * NNODES + i];
        const int4* adj4 = (const int4*)(adj + (size_t)i * NNODES);
        const float4* f2q = (const float4*)s_f2;

        float ev[16];
        float lmax = -3.4e38f;
#pragma unroll
        for (int t = 0; t < 4; t++) {
            int q = ln + 32 * t;
            int4 am = adj4[q];
            float4 fv = f2q[q];
            float e0 = f1i + fv.x; e0 = (e0 > 0.f) ? e0 : ALPHA * e0; e0 = (am.x > 0) ? e0 : NEGBIG;
            float e1 = f1i + fv.y; e1 = (e1 > 0.f) ? e1 : ALPHA * e1; e1 = (am.y > 0) ? e1 : NEGBIG;
            float e2 = f1i + fv.z; e2 = (e2 > 0.f) ? e2 : ALPHA * e2; e2 = (am.z > 0) ? e2 : NEGBIG;
            float e3 = f1i + fv.w; e3 = (e3 > 0.f) ? e3 : ALPHA * e3; e3 = (am.w > 0) ? e3 : NEGBIG;
            ev[4 * t]     = e0; ev[4 * t + 1] = e1;
            ev[4 * t + 2] = e2; ev[4 * t + 3] = e3;
            lmax = fmaxf(lmax, fmaxf(fmaxf(e0, e1), fmaxf(e2, e3)));
        }
#pragma unroll
        for (int o = 16; o; o >>= 1)
            lmax = fmaxf(lmax, __shfl_xor_sync(0xffffffffu, lmax, o));

        float lsum = 0.f;
        float4* spr = (float4*)(sp + r * 512);
#pragma unroll
        for (int t = 0; t < 4; t++) {
            int q = ln + 32 * t;
            float4 pv;
            pv.x = __expf(ev[4 * t]     - lmax);
            pv.y = __expf(ev[4 * t + 1] - lmax);
            pv.z = __expf(ev[4 * t + 2] - lmax);
            pv.w = __expf(ev[4 * t + 3] - lmax);
            spr[q] = pv;
            lsum += pv.x + pv.y + pv.z + pv.w;
        }
#pragma unroll
        for (int o = 16; o; o >>= 1)
            lsum += __shfl_xor_sync(0xffffffffu, lsum, o);
        if (ln == 0) ssum[r] = lsum;
    }
    __syncthreads();
}

__device__ __forceinline__ void att_agg_phase(
    const float* sp, float* sWh, const float* __restrict__ Whb,
    int p, int dq, float& a00, float& a01, float& a10, float& a11, int tid)
{
    a00 = a01 = a10 = a11 = 0.f;

    float buf[16];
#pragma unroll
    for (int t = 0; t < 16; t++) {
        int idx = tid + t * 256;
        buf[t] = Whb[(size_t)(idx >> 6) * 64 + (idx & 63)];
    }

    for (int jt = 0; jt < 8; jt++) {
#pragma unroll
        for (int t = 0; t < 16; t++) {
            int idx = tid + t * 256;
            sWh[(idx >> 6) * 66 + (idx & 63)] = buf[t];
        }
        __syncthreads();
        if (jt < 7) {
#pragma unroll
            for (int t = 0; t < 16; t++) {
                int idx = tid + t * 256;
                buf[t] = Whb[(size_t)((jt + 1) * 64 + (idx >> 6)) * 64 + (idx & 63)];
            }
        }
        const float4* p0q = (const float4*)(sp + (2 * p) * 512 + jt * 64);
        const float4* p1q = (const float4*)(sp + (2 * p + 1) * 512 + jt * 64);
#pragma unroll
        for (int j4 = 0; j4 < 16; j4++) {
            float4 pa = p0q[j4];
            float4 pb = p1q[j4];
            float2 wv0 = ((const float2*)(sWh + (4 * j4 + 0) * 66))[dq];
            float2 wv1 = ((const float2*)(sWh + (4 * j4 + 1) * 66))[dq];
            float2 wv2 = ((const float2*)(sWh + (4 * j4 + 2) * 66))[dq];
            float2 wv3 = ((const float2*)(sWh + (4 * j4 + 3) * 66))[dq];
            a00 = fmaf(pa.x, wv0.x, a00); a01 = fmaf(pa.x, wv0.y, a01);
            a10 = fmaf(pb.x, wv0.x, a10); a11 = fmaf(pb.x, wv0.y, a11);
            a00 = fmaf(pa.y, wv1.x, a00); a01 = fmaf(pa.y, wv1.y, a01);
            a10 = fmaf(pb.y, wv1.x, a10); a11 = fmaf(pb.y, wv1.y, a11);
            a00 = fmaf(pa.z, wv2.x, a00); a01 = fmaf(pa.z, wv2.y, a01);
            a10 = fmaf(pb.z, wv2.x, a10); a11 = fmaf(pb.z, wv2.y, a11);
            a00 = fmaf(pa.w, wv3.x, a00); a01 = fmaf(pa.w, wv3.y, a01);
            a10 = fmaf(pb.w, wv3.x, a10); a11 = fmaf(pb.w, wv3.y, a11);
        }
        __syncthreads();
    }
}

// ---------------- Stage B: attention layer1 + fused gat_pre2 (per batch) ----
__global__ void __launch_bounds__(256)
gat_att1_kernel(const float* __restrict__ Wh, const float* __restrict__ f1,
                const float* __restrict__ f2, const int* __restrict__ adj,
                const float* __restrict__ W2, const float* __restrict__ a2,
                float* __restrict__ Wh2, float* __restrict__ f1o, float* __restrict__ f2o,
                int b)
{
    extern __shared__ float dsm[];
    float* sp   = dsm + A_SP;
    float* sWh  = dsm + A_SWH;
    float* s_f2 = dsm + A_F2;
    float* s_hl = dsm + A_HL;
    float* ssum = dsm + A_SUM;

    const int i0  = blockIdx.x * 16;
    const int tid = threadIdx.x;
    const int p   = tid >> 5;
    const int dq  = tid & 31;

    att_softmax_phase(sp, s_f2, ssum, f1, f2, adj, b, i0, tid);

    float a00, a01, a10, a11;
    att_agg_phase(sp, sWh, Wh + (size_t)b * NNODES * HID, p, dq, a00, a01, a10, a11, tid);

    {
        float inv0 = 1.f / ssum[2 * p];
        float inv1 = 1.f / ssum[2 * p + 1];
        ((float2*)(s_hl + (2 * p) * 64))[dq] =
            make_float2(fmaxf(a00 * inv0, 0.f), fmaxf(a01 * inv0, 0.f));
        ((float2*)(s_hl + (2 * p + 1) * 64))[dq] =
            make_float2(fmaxf(a10 * inv1, 0.f), fmaxf(a11 * inv1, 0.f));
    }
#pragma unroll
    for (int t = 0; t < 16; t++) {
        int idx = tid + t * 256;
        sWh[(idx >> 6) * 66 + (idx & 63)] = W2[idx];
    }
    __syncthreads();

    {
        float w00 = 0.f, w01 = 0.f, w10 = 0.f, w11 = 0.f;
        const float* h0r = s_hl + (2 * p) * 64;
        const float* h1r = h0r + 64;
#pragma unroll 8
        for (int k = 0; k < 64; k++) {
            float2 wv = ((const float2*)(sWh + k * 66))[dq];
            float ha = h0r[k], hb = h1r[k];
            w00 = fmaf(ha, wv.x, w00); w01 = fmaf(ha, wv.y, w01);
            w10 = fmaf(hb, wv.x, w10); w11 = fmaf(hb, wv.y, w11);
        }
        const int row0 = b * NNODES + i0 + 2 * p;
        ((float2*)(Wh2 + (size_t)row0 * 64))[dq]       = make_float2(w00, w01);
        ((float2*)(Wh2 + (size_t)(row0 + 1) * 64))[dq] = make_float2(w10, w11);

        const int d0 = 2 * dq;
        const float ax = __ldg(a2 + d0),      ay = __ldg(a2 + d0 + 1);
        const float bx = __ldg(a2 + 64 + d0), by = __ldg(a2 + 64 + d0 + 1);
        float u0 = w00 * ax + w01 * ay;
        float v0 = w00 * bx + w01 * by;
        float u1 = w10 * ax + w11 * ay;
        float v1 = w10 * bx + w11 * by;
#pragma unroll
        for (int o = 16; o; o >>= 1) {
            u0 += __shfl_down_sync(0xffffffffu, u0, o);
            v0 += __shfl_down_sync(0xffffffffu, v0, o);
            u1 += __shfl_down_sync(0xffffffffu, u1, o);
            v1 += __shfl_down_sync(0xffffffffu, v1, o);
        }
        if (dq == 0) {
            f1o[row0]     = u0;
            f2o[row0]     = v0;
            f1o[row0 + 1] = u1;
            f2o[row0 + 1] = v1;
        }
    }
}

// ---------------- Stage C: attention layer2 (per batch) ----------
__global__ void __launch_bounds__(256)
gat_att2_kernel(const float* __restrict__ Wh, const float* __restrict__ f1,
                const float* __restrict__ f2, const int* __restrict__ adj,
                float* __restrict__ out, int b)
{
    extern __shared__ float dsm[];
    float* sp   = dsm + A_SP;
    float* sWh  = dsm + A_SWH;
    float* s_f2 = dsm + A_F2;
    float* ssum = dsm + A_SUM;

    const int i0  = blockIdx.x * 16;
    const int tid = threadIdx.x;
    const int p   = tid >> 5;
    const int dq  = tid & 31;

    att_softmax_phase(sp, s_f2, ssum, f1, f2, adj, b, i0, tid);

    float a00, a01, a10, a11;
    att_agg_phase(sp, sWh, Wh + (size_t)b * NNODES * HID, p, dq, a00, a01, a10, a11, tid);

    const float inv0 = 1.f / ssum[2 * p];
    const float inv1 = 1.f / ssum[2 * p + 1];
    const int row0 = b * NNODES + i0 + 2 * p;
    ((float2*)(out + (size_t)row0 * 64))[dq]       = make_float2(a00 * inv0, a01 * inv0);
    ((float2*)(out + (size_t)(row0 + 1) * 64))[dq] = make_float2(a10 * inv1, a11 * inv1);
}

// ---------------- Stage D: edge MLP (per batch) --------
#define EPB 16
__global__ void __launch_bounds__(1024)
edge_mlp_kernel(const float* __restrict__ h, const int* __restrict__ eidx,
                const float* __restrict__ fc1w, const float* __restrict__ fc1b,
                const float* __restrict__ fc2w, const float* __restrict__ fc2b,
                float* __restrict__ out, int b)
{
    __shared__ float sw[128 * 64];
    __shared__ float she[EPB][128];
    __shared__ float sr[EPB][2];

    const int tid = threadIdx.x;

    for (int i = tid; i < 128 * 64; i += 1024) sw[i] = fc1w[i];

    const int es = tid >> 6;
    const int t  = tid & 63;
    const int e  = blockIdx.x * EPB + es;

    const int i1 = eidx[2 * e];
    const int i2 = eidx[2 * e + 1];
    she[es][t]      = h[((size_t)b * NNODES + i1) * HID + t];
    she[es][64 + t] = h[((size_t)b * NNODES + i2) * HID + t];
    __syncthreads();

    float acc = fc1b[t];
    const float* sher = she[es];
#pragma unroll 8
    for (int k = 0; k < 128; k++)
        acc = fmaf(sher[k], sw[k * 64 + t], acc);
    acc = fmaxf(acc, 0.f);

    float v = acc * fc2w[t];
#pragma unroll
    for (int o = 16; o; o >>= 1)
        v += __shfl_down_sync(0xffffffffu, v, o);
    if ((t & 31) == 0) sr[es][t >> 5] = v;
    __syncthreads();
    if (t == 0) {
        float z = sr[es][0] + sr[es][1] + fc2b[0];
        out[(size_t)b * NEDGES + e] = 1.f / (1.f + expf(-z));
    }
}

// ---------------- launch: 2-stream per-batch pipeline ----------------
extern "C" void kernel_launch(void* const* d_in, const int* in_sizes, int n_in,
                              void* d_out, int out_size)
{
    const float* x    = (const float*)d_in[0];
    const int*   adj  = (const int*)  d_in[1];
    const int*   eidx = (const int*)  d_in[2];
    const float* w1   = (const float*)d_in[3];
    const float* b1   = (const float*)d_in[4];
    const float* w2   = (const float*)d_in[5];
    const float* b2   = (const float*)d_in[6];
    const float* W1   = (const float*)d_in[7];
    const float* a1   = (const float*)d_in[8];
    const float* W2   = (const float*)d_in[9];
    const float* a2   = (const float*)d_in[10];
    const float* fc1w = (const float*)d_in[11];
    const float* fc1b = (const float*)d_in[12];
    const float* fc2w = (const float*)d_in[13];
    const float* fc2b = (const float*)d_in[14];
    float* out = (float*)d_out;

    float *Wh1, *Wh2, *h2, *f1a, *f2a, *f1b, *f2b;
    cudaGetSymbolAddress((void**)&Wh1, g_Wh1);
    cudaGetSymbolAddress((void**)&Wh2, g_Wh2);
    cudaGetSymbolAddress((void**)&h2,  g_h2);
    cudaGetSymbolAddress((void**)&f1a, g_f1a);
    cudaGetSymbolAddress((void**)&f2a, g_f2a);
    cudaGetSymbolAddress((void**)&f1b, g_f1b);
    cudaGetSymbolAddress((void**)&f2b, g_f2b);

    // one-time host resources (no device memory involved)
    static cudaStream_t s_conv = nullptr, s_att = nullptr;
    static cudaEvent_t ev_pack, ev_conv[BATCH], ev_conv_done, ev_att_done;
    static bool inited = false;
    if (!inited) {
        cudaStreamCreateWithFlags(&s_conv, cudaStreamNonBlocking);
        cudaStreamCreateWithFlags(&s_att,  cudaStreamNonBlocking);
        cudaEventCreateWithFlags(&ev_pack, cudaEventDisableTiming);
        for (int b = 0; b < BATCH; b++)
            cudaEventCreateWithFlags(&ev_conv[b], cudaEventDisableTiming);
        cudaEventCreateWithFlags(&ev_conv_done, cudaEventDisableTiming);
        cudaEventCreateWithFlags(&ev_att_done,  cudaEventDisableTiming);
        inited = true;
    }

    cudaFuncSetAttribute(conv_fused_kernel,
                         cudaFuncAttributeMaxDynamicSharedMemorySize,
                         CONV_SMEM_BYTES);
    cudaFuncSetAttribute(gat_att1_kernel,
                         cudaFuncAttributeMaxDynamicSharedMemorySize,
                         ATT_SMEM_BYTES);
    cudaFuncSetAttribute(gat_att2_kernel,
                         cudaFuncAttributeMaxDynamicSharedMemorySize,
                         ATT_SMEM_BYTES);

    // origin stream: pack, then fork both worker streams
    pack_w2_kernel<<<(160 * 72 + 255) / 256, 256>>>(w2);
    cudaEventRecord(ev_pack, 0);
    cudaStreamWaitEvent(s_conv, ev_pack, 0);
    cudaStreamWaitEvent(s_att,  ev_pack, 0);

    for (int b = 0; b < BATCH; b++) {
        conv_fused_kernel<<<CONV_BGRID, 256, CONV_SMEM_BYTES, s_conv>>>(
            x, w1, b1, b2, W1, a1, Wh1, f1a, f2a, b);
        cudaEventRecord(ev_conv[b], s_conv);

        cudaStreamWaitEvent(s_att, ev_conv[b], 0);
        gat_att1_kernel<<<NNODES / 16, 256, ATT_SMEM_BYTES, s_att>>>(
            Wh1, f1a, f2a, adj, W2, a2, Wh2, f1b, f2b, b);
        gat_att2_kernel<<<NNODES / 16, 256, ATT_SMEM_BYTES, s_att>>>(
            Wh2, f1b, f2b, adj, h2, b);
        edge_mlp_kernel<<<NEDGES / EPB, 1024, 0, s_att>>>(
            h2, eidx, fc1w, fc1b, fc2w, fc2b, out, b);
    }

    // join both streams back to origin
    cudaEventRecord(ev_conv_done, s_conv);
    cudaEventRecord(ev_att_done,  s_att);
    cudaStreamWaitEvent(0, ev_conv_done, 0);
    cudaStreamWaitEvent(0, ev_att_done, 0);
}

// round 15
// speedup vs baseline: 1.7515x; 1.7515x over previous
#include <cuda_runtime.h>
#include <math.h>
#include <stdint.h>

#define BATCH   8
#define SEQ     200
#define NNODES  512
#define HID     64
#define NEDGES  2048
#define ALPHA   0.2f
#define NEGBIG  -9.0e15f
#define CONV_GRID 304

// ---------------- scratch (device globals, no allocation) ----------------
__device__ float g_Wh1[BATCH * NNODES * HID];
__device__ float g_Wh2[BATCH * NNODES * HID];
__device__ float g_h2[BATCH * NNODES * HID];
__device__ float g_f1a[BATCH * NNODES];
__device__ float g_f2a[BATCH * NNODES];
__device__ float g_f1b[BATCH * NNODES];
__device__ float g_f2b[BATCH * NNODES];
__device__ uint4 g_w2t[20 * 32 * 20 / 4];   // fragment-major tf32 conv2 weights

// ---------------- tf32 helpers ----------------
__device__ __forceinline__ uint32_t f2tf32(float f) {
    uint32_t r;
    asm("cvt.rna.tf32.f32 %0, %1;" : "=r"(r) : "f"(f));
    return r;
}
__device__ __forceinline__ void mma_tf32(float* c,
                                         uint32_t a0, uint32_t a1, uint32_t a2, uint32_t a3,
                                         uint32_t b0, uint32_t b1) {
    asm volatile(
        "mma.sync.aligned.m16n8k8.row.col.f32.tf32.tf32.f32 "
        "{%0,%1,%2,%3}, {%4,%5,%6,%7}, {%8,%9}, {%0,%1,%2,%3};"
        : "+f"(c[0]), "+f"(c[1]), "+f"(c[2]), "+f"(c[3])
        : "r"(a0), "r"(a1), "r"(a2), "r"(a3), "r"(b0), "r"(b1));
}

// ---------------- setup: conv2 weights -> fragment-major ------
// word i = (kc*32 + lane)*20 + slot; slot<16 used, 16..19 pad.
// slot<8 : bb0[nt=slot],   r = kc*8 + (lane&3)
// slot>=8: bb1[nt=slot-8], r = kc*8 + 4 + (lane&3)
// value = tf32(w2[(nt*8 + (lane>>2))*160 + r])
__global__ void pack_w2_kernel(const float* __restrict__ w2) {
    int i = blockIdx.x * blockDim.x + threadIdx.x;
    if (i >= 20 * 32 * 20) return;
    int slot = i % 20;
    int lane = (i / 20) & 31;
    int kc   = i / 640;
    uint32_t v = 0;
    if (slot < 16) {
        int g  = lane >> 2, t4 = lane & 3;
        int nt = slot & 7;
        int r  = kc * 8 + t4 + ((slot >= 8) ? 4 : 0);
        v = f2tf32(w2[(nt * 8 + g) * 160 + r]);
    }
    ((uint32_t*)g_w2t)[i] = v;
}

// ---------------- Stage A: persistent conv + fused gat_pre1 ----------
#define H1W   264
#define S_H1_OFF  0
#define S_BF_OFF  (32 * H1W)                  // 8448
#define S_IN_OFF  (S_BF_OFF + 12800)          // 21248
#define S_W1_OFF  (S_IN_OFF + 2 * 208)        // 21664
#define S_RED_OFF (S_W1_OFF + 320)            // 21984
#define S_H0_OFF  (S_RED_OFF + 512)           // 22496
#define S_PT_OFF  (S_H0_OFF + 64)             // 22560
#define CONV_SMEM_FLOATS (S_PT_OFF + 256)     // 22816
#define CONV_SMEM_BYTES  (CONV_SMEM_FLOATS * 4)

__global__ void __launch_bounds__(256, 2)
conv_fused_kernel(const float* __restrict__ x,
                  const float* __restrict__ w1, const float* __restrict__ b1,
                  const float* __restrict__ b2,
                  const float* __restrict__ W1, const float* __restrict__ a1,
                  float* __restrict__ Wh, float* __restrict__ f1, float* __restrict__ f2)
{
    extern __shared__ float sm[];
    float* s_h1  = sm + S_H1_OFF;
    float* s_bf  = sm + S_BF_OFF;
    float* s_in  = sm + S_IN_OFF;
    float* s_w1  = sm + S_W1_OFF;
    float* s_red = sm + S_RED_OFF;
    float* s_h0  = sm + S_H0_OFF;
    float* s_pt  = sm + S_PT_OFF;

    const int tid = threadIdx.x;

    // one-time per block: weights + input pads
    for (int i = tid; i < 320; i += 256) s_w1[i] = w1[i];
    {
        uint4* dst = (uint4*)s_bf;
        for (int i = tid; i < 3200; i += 256) dst[i] = g_w2t[i];
    }
    // zero pads: per channel c, indices {0,1} and [202,208)
    if (tid < 16) {
        int c = tid >> 3, q = tid & 7;
        int idx = (q < 2) ? q : (200 + q);     // 0,1,202..207
        s_in[c * 208 + idx] = 0.f;
    }

    const int warp = tid >> 5;
    const int lane = tid & 31;
    const int g    = lane >> 2;
    const int t4   = lane & 3;

    // prefetch decomposition
    const int sA = tid >> 1,          cA = tid & 1;
    const int sB = (tid + 256) >> 1,  cB = tid & 1;
    const bool has2 = (tid < 144);

    // prefetch first node's input
    float xv0 = 0.f, xv1 = 0.f;
    {
        const int bn0 = blockIdx.x;
        const int b0  = bn0 >> 9;
        const int n0  = bn0 & 511;
        const float* xb = x + (size_t)b0 * SEQ * (NNODES * 2) + 2 * n0;
        xv0 = xb[(size_t)sA * (NNODES * 2) + cA];
        if (has2) xv1 = xb[(size_t)sB * (NNODES * 2) + cB];
    }

    for (int bn = blockIdx.x; bn < BATCH * NNODES; bn += CONV_GRID) {
        s_in[cA * 208 + 2 + sA] = xv0;
        if (has2) s_in[cB * 208 + 2 + sB] = xv1;
        __syncthreads();

        // conv1 + relu -> tf32 h1 (sliding window)
        {
            const int ic = tid >> 3;
            const int j  = tid & 7;
            const int sj = 25 * j;
            const float b1i = b1[ic];
            const float* w  = s_w1 + ic * 10;
            uint32_t* h1u = (uint32_t*)(s_h1 + ic * H1W);

            float a0[29], a1v[29];
            const float* i0 = s_in + sj;
            const float* i1 = s_in + 208 + sj;
#pragma unroll
            for (int q = 0; q < 29; q++) { a0[q] = i0[q]; a1v[q] = i1[q]; }

#pragma unroll
            for (int q = 0; q < 25; q++) {
                float acc = b1i;
#pragma unroll
                for (int k = 0; k < 5; k++)
                    acc = fmaf(w[k], a0[q + k], fmaf(w[5 + k], a1v[q + k], acc));
                h1u[2 + sj + q] = f2tf32(fmaxf(acc, 0.f));
            }
            if (j == 0) { h1u[0] = 0u; h1u[1] = 0u; }
            if (j == 7) {
#pragma unroll
                for (int q = 0; q < 10; q++) h1u[202 + q] = 0u;
            }
        }
        __syncthreads();

        // prefetch NEXT node's input (hidden under GEMM)
        {
            const int bnn = bn + CONV_GRID;
            if (bnn < BATCH * NNODES) {
                const int bb = bnn >> 9;
                const int nn = bnn & 511;
                const float* xb = x + (size_t)bb * SEQ * (NNODES * 2) + 2 * nn;
                xv0 = xb[(size_t)sA * (NNODES * 2) + cA];
                if (has2) xv1 = xb[(size_t)sB * (NNODES * 2) + cB];
            }
        }

        // -------- tensor-core GEMM (fragment-major B, uint4 LDS) --------
        const uint32_t* h1u = (const uint32_t*)s_h1;

        float c[2][8][4];
#pragma unroll
        for (int mt = 0; mt < 2; mt++)
#pragma unroll
            for (int nt = 0; nt < 8; nt++)
#pragma unroll
                for (int q = 0; q < 4; q++) c[mt][nt][q] = 0.f;

#pragma unroll 2
        for (int kc = 0; kc < 20; kc++) {
            const uint4* bk = (const uint4*)(s_bf + (kc * 32 + lane) * 20);
            uint4 q0 = bk[0], q1 = bk[1], q2 = bk[2], q3 = bk[3];
            uint32_t bb0[8] = {q0.x, q0.y, q0.z, q0.w, q1.x, q1.y, q1.z, q1.w};
            uint32_t bb1[8] = {q2.x, q2.y, q2.z, q2.w, q3.x, q3.y, q3.z, q3.w};

            const int r0 = kc * 8 + t4;
            const int r1 = r0 + 4;
            const int ic0 = r0 / 5, k0 = r0 - ic0 * 5;
            const int ic1 = r1 / 5, k1 = r1 - ic1 * 5;
            const int ao0 = ic0 * H1W + k0;
            const int ao1 = ic1 * H1W + k1;
#pragma unroll
            for (int mt = 0; mt < 2; mt++) {
                const int tile = warp + 8 * mt;
                if (tile >= 13) continue;
                const int sb = tile * 16 + g;
                uint32_t a0 = h1u[ao0 + sb];
                uint32_t a1 = h1u[ao0 + sb + 8];
                uint32_t a2 = h1u[ao1 + sb];
                uint32_t a3 = h1u[ao1 + sb + 8];
#pragma unroll
                for (int nt = 0; nt < 8; nt++)
                    mma_tf32(c[mt][nt], a0, a1, a2, a3, bb0[nt], bb1[nt]);
            }
        }

        // -------- epilogue: bias + relu + masked sum --------
#pragma unroll
        for (int nt = 0; nt < 8; nt++) {
            const int n0 = nt * 8 + 2 * t4;
            const float bias0 = b2[n0], bias1 = b2[n0 + 1];
            float sm0 = 0.f, sm1 = 0.f;
#pragma unroll
            for (int mt = 0; mt < 2; mt++) {
                const int tile = warp + 8 * mt;
                if (tile >= 13) continue;
                const int rA = tile * 16 + g;
                const int rB = rA + 8;
                if (rA < 200) {
                    sm0 += fmaxf(c[mt][nt][0] + bias0, 0.f);
                    sm1 += fmaxf(c[mt][nt][1] + bias1, 0.f);
                }
                if (rB < 200) {
                    sm0 += fmaxf(c[mt][nt][2] + bias0, 0.f);
                    sm1 += fmaxf(c[mt][nt][3] + bias1, 0.f);
                }
            }
#pragma unroll
            for (int off = 16; off >= 4; off >>= 1) {
                sm0 += __shfl_down_sync(0xffffffffu, sm0, off);
                sm1 += __shfl_down_sync(0xffffffffu, sm1, off);
            }
            if (lane < 4) {
                s_red[warp * 64 + nt * 8 + 2 * lane]     = sm0;
                s_red[warp * 64 + nt * 8 + 2 * lane + 1] = sm1;
            }
        }
        __syncthreads();

        if (tid < 64) {
            float t = 0.f;
#pragma unroll
            for (int w = 0; w < 8; w++) t += s_red[w * 64 + tid];
            s_h0[tid] = t * (1.f / 200.f);
        }
        __syncthreads();

        // -------- fused gat_pre1 --------
        {
            const int kq = tid >> 6;
            const int d  = tid & 63;
            float acc = 0.f;
#pragma unroll
            for (int i = 0; i < 16; i++) {
                int k = kq * 16 + i;
                acc = fmaf(s_h0[k], __ldg(W1 + k * 64 + d), acc);
            }
            s_pt[kq * 64 + d] = acc;
        }
        __syncthreads();

        if (tid < 64) {
            float wh = s_pt[tid] + s_pt[64 + tid] + s_pt[128 + tid] + s_pt[192 + tid];
            Wh[(size_t)bn * 64 + tid] = wh;
            float v1 = wh * __ldg(a1 + tid);
            float v2 = wh * __ldg(a1 + 64 + tid);
#pragma unroll
            for (int o = 16; o; o >>= 1) {
                v1 += __shfl_down_sync(0xffffffffu, v1, o);
                v2 += __shfl_down_sync(0xffffffffu, v2, o);
            }
            if ((tid & 31) == 0) {
                s_pt[(tid >> 5) * 2]     = v1;
                s_pt[(tid >> 5) * 2 + 1] = v2;
            }
        }
        __syncthreads();
        if (tid == 0) {
            f1[bn] = s_pt[0] + s_pt[2];
            f2[bn] = s_pt[1] + s_pt[3];
        }
        __syncthreads();
    }
}

// ---------------- attention smem layout (dynamic, R9 shapes) ----
#define A_SP   0
#define A_SWH  8192
#define A_F2   12416
#define A_HL   12928
#define A_SUM  13952
#define ATT_SMEM_FLOATS 13968
#define ATT_SMEM_BYTES  (ATT_SMEM_FLOATS * 4)

// phase A: 8 warps x 2 rows; int4 adj + smem f2 + __expf
__device__ __forceinline__ void att_softmax_phase(
    float* sp, float* s_f2, float* ssum,
    const float* __restrict__ f1, const float* __restrict__ f2,
    const int* __restrict__ adj, int b, int i0, int tid)
{
    const int w  = tid >> 5;
    const int ln = tid & 31;

    for (int i = tid; i < 512; i += 256) s_f2[i] = f2[b * NNODES + i];
    __syncthreads();

#pragma unroll
    for (int rr = 0; rr < 2; rr++) {
        const int r = w * 2 + rr;
        const int i = i0 + r;
        const float f1i = f1[b * NNODES + i];
        const int4* adj4 = (const int4*)(adj + (size_t)i * NNODES);
        const float4* f2q = (const float4*)s_f2;

        float ev[16];
        float lmax = -3.4e38f;
#pragma unroll
        for (int t = 0; t < 4; t++) {
            int q = ln + 32 * t;
            int4 am = adj4[q];
            float4 fv = f2q[q];
            float e0 = f1i + fv.x; e0 = (e0 > 0.f) ? e0 : ALPHA * e0; e0 = (am.x > 0) ? e0 : NEGBIG;
            float e1 = f1i + fv.y; e1 = (e1 > 0.f) ? e1 : ALPHA * e1; e1 = (am.y > 0) ? e1 : NEGBIG;
            float e2 = f1i + fv.z; e2 = (e2 > 0.f) ? e2 : ALPHA * e2; e2 = (am.z > 0) ? e2 : NEGBIG;
            float e3 = f1i + fv.w; e3 = (e3 > 0.f) ? e3 : ALPHA * e3; e3 = (am.w > 0) ? e3 : NEGBIG;
            ev[4 * t]     = e0; ev[4 * t + 1] = e1;
            ev[4 * t + 2] = e2; ev[4 * t + 3] = e3;
            lmax = fmaxf(lmax, fmaxf(fmaxf(e0, e1), fmaxf(e2, e3)));
        }
#pragma unroll
        for (int o = 16; o; o >>= 1)
            lmax = fmaxf(lmax, __shfl_xor_sync(0xffffffffu, lmax, o));

        float lsum = 0.f;
        float4* spr = (float4*)(sp + r * 512);
#pragma unroll
        for (int t = 0; t < 4; t++) {
            int q = ln + 32 * t;
            float4 pv;
            pv.x = __expf(ev[4 * t]     - lmax);
            pv.y = __expf(ev[4 * t + 1] - lmax);
            pv.z = __expf(ev[4 * t + 2] - lmax);
            pv.w = __expf(ev[4 * t + 3] - lmax);
            spr[q] = pv;
            lsum += pv.x + pv.y + pv.z + pv.w;
        }
#pragma unroll
        for (int o = 16; o; o >>= 1)
            lsum += __shfl_xor_sync(0xffffffffu, lsum, o);
        if (ln == 0) ssum[r] = lsum;
    }
    __syncthreads();
}

// phase B: 16 rows x 64 d, 4 outputs/thread; float4 p-loads + LDG prefetch
__device__ __forceinline__ void att_agg_phase(
    const float* sp, float* sWh, const float* __restrict__ Whb,
    int p, int dq, float& a00, float& a01, float& a10, float& a11, int tid)
{
    a00 = a01 = a10 = a11 = 0.f;

    float buf[16];
#pragma unroll
    for (int t = 0; t < 16; t++) {
        int idx = tid + t * 256;
        buf[t] = Whb[(size_t)(idx >> 6) * 64 + (idx & 63)];
    }

    for (int jt = 0; jt < 8; jt++) {
#pragma unroll
        for (int t = 0; t < 16; t++) {
            int idx = tid + t * 256;
            sWh[(idx >> 6) * 66 + (idx & 63)] = buf[t];
        }
        __syncthreads();
        if (jt < 7) {
#pragma unroll
            for (int t = 0; t < 16; t++) {
                int idx = tid + t * 256;
                buf[t] = Whb[(size_t)((jt + 1) * 64 + (idx >> 6)) * 64 + (idx & 63)];
            }
        }
        const float4* p0q = (const float4*)(sp + (2 * p) * 512 + jt * 64);
        const float4* p1q = (const float4*)(sp + (2 * p + 1) * 512 + jt * 64);
#pragma unroll
        for (int j4 = 0; j4 < 16; j4++) {
            float4 pa = p0q[j4];
            float4 pb = p1q[j4];
            float2 wv0 = ((const float2*)(sWh + (4 * j4 + 0) * 66))[dq];
            float2 wv1 = ((const float2*)(sWh + (4 * j4 + 1) * 66))[dq];
            float2 wv2 = ((const float2*)(sWh + (4 * j4 + 2) * 66))[dq];
            float2 wv3 = ((const float2*)(sWh + (4 * j4 + 3) * 66))[dq];
            a00 = fmaf(pa.x, wv0.x, a00); a01 = fmaf(pa.x, wv0.y, a01);
            a10 = fmaf(pb.x, wv0.x, a10); a11 = fmaf(pb.x, wv0.y, a11);
            a00 = fmaf(pa.y, wv1.x, a00); a01 = fmaf(pa.y, wv1.y, a01);
            a10 = fmaf(pb.y, wv1.x, a10); a11 = fmaf(pb.y, wv1.y, a11);
            a00 = fmaf(pa.z, wv2.x, a00); a01 = fmaf(pa.z, wv2.y, a01);
            a10 = fmaf(pb.z, wv2.x, a10); a11 = fmaf(pb.z, wv2.y, a11);
            a00 = fmaf(pa.w, wv3.x, a00); a01 = fmaf(pa.w, wv3.y, a01);
            a10 = fmaf(pb.w, wv3.x, a10); a11 = fmaf(pb.w, wv3.y, a11);
        }
        __syncthreads();
    }
}

// ---------------- Stage B: attention layer1 + fused gat_pre2 ----------
__global__ void __launch_bounds__(256)
gat_att1_kernel(const float* __restrict__ Wh, const float* __restrict__ f1,
                const float* __restrict__ f2, const int* __restrict__ adj,
                const float* __restrict__ W2, const float* __restrict__ a2,
                float* __restrict__ Wh2, float* __restrict__ f1o, float* __restrict__ f2o)
{
    extern __shared__ float dsm[];
    float* sp   = dsm + A_SP;
    float* sWh  = dsm + A_SWH;
    float* s_f2 = dsm + A_F2;
    float* s_hl = dsm + A_HL;
    float* ssum = dsm + A_SUM;

    const int blk = blockIdx.x;
    const int b   = blk >> 5;
    const int i0  = (blk & 31) * 16;
    const int tid = threadIdx.x;
    const int p   = tid >> 5;
    const int dq  = tid & 31;

    att_softmax_phase(sp, s_f2, ssum, f1, f2, adj, b, i0, tid);

    float a00, a01, a10, a11;
    att_agg_phase(sp, sWh, Wh + (size_t)b * NNODES * HID, p, dq, a00, a01, a10, a11, tid);

    {
        float inv0 = 1.f / ssum[2 * p];
        float inv1 = 1.f / ssum[2 * p + 1];
        ((float2*)(s_hl + (2 * p) * 64))[dq] =
            make_float2(fmaxf(a00 * inv0, 0.f), fmaxf(a01 * inv0, 0.f));
        ((float2*)(s_hl + (2 * p + 1) * 64))[dq] =
            make_float2(fmaxf(a10 * inv1, 0.f), fmaxf(a11 * inv1, 0.f));
    }
#pragma unroll
    for (int t = 0; t < 16; t++) {
        int idx = tid + t * 256;
        sWh[(idx >> 6) * 66 + (idx & 63)] = W2[idx];
    }
    __syncthreads();

    {
        float w00 = 0.f, w01 = 0.f, w10 = 0.f, w11 = 0.f;
        const float* h0r = s_hl + (2 * p) * 64;
        const float* h1r = h0r + 64;
#pragma unroll 8
        for (int k = 0; k < 64; k++) {
            float2 wv = ((const float2*)(sWh + k * 66))[dq];
            float ha = h0r[k], hb = h1r[k];
            w00 = fmaf(ha, wv.x, w00); w01 = fmaf(ha, wv.y, w01);
            w10 = fmaf(hb, wv.x, w10); w11 = fmaf(hb, wv.y, w11);
        }
        const int row0 = b * NNODES + i0 + 2 * p;
        ((float2*)(Wh2 + (size_t)row0 * 64))[dq]       = make_float2(w00, w01);
        ((float2*)(Wh2 + (size_t)(row0 + 1) * 64))[dq] = make_float2(w10, w11);

        const int d0 = 2 * dq;
        const float ax = __ldg(a2 + d0),      ay = __ldg(a2 + d0 + 1);
        const float bx = __ldg(a2 + 64 + d0), by = __ldg(a2 + 64 + d0 + 1);
        float u0 = w00 * ax + w01 * ay;
        float v0 = w00 * bx + w01 * by;
        float u1 = w10 * ax + w11 * ay;
        float v1 = w10 * bx + w11 * by;
#pragma unroll
        for (int o = 16; o; o >>= 1) {
            u0 += __shfl_down_sync(0xffffffffu, u0, o);
            v0 += __shfl_down_sync(0xffffffffu, v0, o);
            u1 += __shfl_down_sync(0xffffffffu, u1, o);
            v1 += __shfl_down_sync(0xffffffffu, v1, o);
        }
        if (dq == 0) {
            f1o[row0]     = u0;
            f2o[row0]     = v0;
            f1o[row0 + 1] = u1;
            f2o[row0 + 1] = v1;
        }
    }
}

// ---------------- Stage C: attention layer2 ----------
__global__ void __launch_bounds__(256)
gat_att2_kernel(const float* __restrict__ Wh, const float* __restrict__ f1,
                const float* __restrict__ f2, const int* __restrict__ adj,
                float* __restrict__ out)
{
    extern __shared__ float dsm[];
    float* sp   = dsm + A_SP;
    float* sWh  = dsm + A_SWH;
    float* s_f2 = dsm + A_F2;
    float* ssum = dsm + A_SUM;

    const int blk = blockIdx.x;
    const int b   = blk >> 5;
    const int i0  = (blk & 31) * 16;
    const int tid = threadIdx.x;
    const int p   = tid >> 5;
    const int dq  = tid & 31;

    att_softmax_phase(sp, s_f2, ssum, f1, f2, adj, b, i0, tid);

    float a00, a01, a10, a11;
    att_agg_phase(sp, sWh, Wh + (size_t)b * NNODES * HID, p, dq, a00, a01, a10, a11, tid);

    const float inv0 = 1.f / ssum[2 * p];
    const float inv1 = 1.f / ssum[2 * p + 1];
    const int row0 = b * NNODES + i0 + 2 * p;
    ((float2*)(out + (size_t)row0 * 64))[dq]       = make_float2(a00 * inv0, a01 * inv0);
    ((float2*)(out + (size_t)(row0 + 1) * 64))[dq] = make_float2(a10 * inv1, a11 * inv1);
}

// ---------------- Stage D: edge MLP (16 edges/block, smem weights) --------
#define EPB 16
__global__ void __launch_bounds__(1024)
edge_mlp_kernel(const float* __restrict__ h, const int* __restrict__ eidx,
                const float* __restrict__ fc1w, const float* __restrict__ fc1b,
                const float* __restrict__ fc2w, const float* __restrict__ fc2b,
                float* __restrict__ out)
{
    __shared__ float sw[128 * 64];
    __shared__ float she[EPB][128];
    __shared__ float sr[EPB][2];

    const int tid = threadIdx.x;
    const int b   = blockIdx.y;

    for (int i = tid; i < 128 * 64; i += 1024) sw[i] = fc1w[i];

    const int es = tid >> 6;
    const int t  = tid & 63;
    const int e  = blockIdx.x * EPB + es;

    const int i1 = eidx[2 * e];
    const int i2 = eidx[2 * e + 1];
    she[es][t]      = h[((size_t)b * NNODES + i1) * HID + t];
    she[es][64 + t] = h[((size_t)b * NNODES + i2) * HID + t];
    __syncthreads();

    float acc = fc1b[t];
    const float* sher = she[es];
#pragma unroll 8
    for (int k = 0; k < 128; k++)
        acc = fmaf(sher[k], sw[k * 64 + t], acc);
    acc = fmaxf(acc, 0.f);

    float v = acc * fc2w[t];
#pragma unroll
    for (int o = 16; o; o >>= 1)
        v += __shfl_down_sync(0xffffffffu, v, o);
    if ((t & 31) == 0) sr[es][t >> 5] = v;
    __syncthreads();
    if (t == 0) {
        float z = sr[es][0] + sr[es][1] + fc2b[0];
        out[(size_t)b * NEDGES + e] = 1.f / (1.f + expf(-z));
    }
}

// ---------------- launch ----------------
extern "C" void kernel_launch(void* const* d_in, const int* in_sizes, int n_in,
                              void* d_out, int out_size)
{
    const float* x    = (const float*)d_in[0];
    const int*   adj  = (const int*)  d_in[1];
    const int*   eidx = (const int*)  d_in[2];
    const float* w1   = (const float*)d_in[3];
    const float* b1   = (const float*)d_in[4];
    const float* w2   = (const float*)d_in[5];
    const float* b2   = (const float*)d_in[6];
    const float* W1   = (const float*)d_in[7];
    const float* a1   = (const float*)d_in[8];
    const float* W2   = (const float*)d_in[9];
    const float* a2   = (const float*)d_in[10];
    const float* fc1w = (const float*)d_in[11];
    const float* fc1b = (const float*)d_in[12];
    const float* fc2w = (const float*)d_in[13];
    const float* fc2b = (const float*)d_in[14];
    float* out = (float*)d_out;

    float *Wh1, *Wh2, *h2, *f1a, *f2a, *f1b, *f2b;
    cudaGetSymbolAddress((void**)&Wh1, g_Wh1);
    cudaGetSymbolAddress((void**)&Wh2, g_Wh2);
    cudaGetSymbolAddress((void**)&h2,  g_h2);
    cudaGetSymbolAddress((void**)&f1a, g_f1a);
    cudaGetSymbolAddress((void**)&f2a, g_f2a);
    cudaGetSymbolAddress((void**)&f1b, g_f1b);
    cudaGetSymbolAddress((void**)&f2b, g_f2b);

    cudaFuncSetAttribute(conv_fused_kernel,
                         cudaFuncAttributeMaxDynamicSharedMemorySize,
                         CONV_SMEM_BYTES);
    cudaFuncSetAttribute(gat_att1_kernel,
                         cudaFuncAttributeMaxDynamicSharedMemorySize,
                         ATT_SMEM_BYTES);
    cudaFuncSetAttribute(gat_att2_kernel,
                         cudaFuncAttributeMaxDynamicSharedMemorySize,
                         ATT_SMEM_BYTES);

    pack_w2_kernel<<<(20 * 32 * 20 + 255) / 256, 256>>>(w2);

    // Stage A: persistent conv with pipelined input prefetch (single stream)
    conv_fused_kernel<<<CONV_GRID, 256, CONV_SMEM_BYTES>>>(
        x, w1, b1, b2, W1, a1, Wh1, f1a, f2a);

    gat_att1_kernel<<<(BATCH * NNODES) / 16, 256, ATT_SMEM_BYTES>>>(
        Wh1, f1a, f2a, adj, W2, a2, Wh2, f1b, f2b);

    gat_att2_kernel<<<(BATCH * NNODES) / 16, 256, ATT_SMEM_BYTES>>>(
        Wh2, f1b, f2b, adj, h2);

    dim3 eg(NEDGES / EPB, BATCH);
    edge_mlp_kernel<<<eg, 1024>>>(h2, eidx, fc1w, fc1b, fc2w, fc2b, out);
}

// round 16
// speedup vs baseline: 1.9494x; 1.1130x over previous
#include <cuda_runtime.h>
#include <math.h>
#include <stdint.h>

#define BATCH   8
#define SEQ     200
#define NNODES  512
#define HID     64
#define NEDGES  2048
#define ALPHA   0.2f
#define NEGBIG  -9.0e15f
#define CONV_GRID 304

// ---------------- scratch (device globals, no allocation) ----------------
__device__ float g_Wh1[BATCH * NNODES * HID];   // tf32-rounded values
__device__ float g_Wh2[BATCH * NNODES * HID];   // tf32-rounded values
__device__ float g_h2[BATCH * NNODES * HID];
__device__ float g_f1a[BATCH * NNODES];
__device__ float g_f2a[BATCH * NNODES];
__device__ float g_f1b[BATCH * NNODES];
__device__ float g_f2b[BATCH * NNODES];
__device__ uint4 g_w2t[160 * 72 / 4];     // tf32, [r][n] transposed, stride 72

// ---------------- tf32 helpers ----------------
__device__ __forceinline__ uint32_t f2tf32(float f) {
    uint32_t r;
    asm("cvt.rna.tf32.f32 %0, %1;" : "=r"(r) : "f"(f));
    return r;
}
__device__ __forceinline__ float tf32v(float f) {
    return __uint_as_float(f2tf32(f));
}
__device__ __forceinline__ void mma_tf32(float* c,
                                         uint32_t a0, uint32_t a1, uint32_t a2, uint32_t a3,
                                         uint32_t b0, uint32_t b1) {
    asm volatile(
        "mma.sync.aligned.m16n8k8.row.col.f32.tf32.tf32.f32 "
        "{%0,%1,%2,%3}, {%4,%5,%6,%7}, {%8,%9}, {%0,%1,%2,%3};"
        : "+f"(c[0]), "+f"(c[1]), "+f"(c[2]), "+f"(c[3])
        : "r"(a0), "r"(a1), "r"(a2), "r"(a3), "r"(b0), "r"(b1));
}

// ---------------- setup: pre-convert conv2 weights (R13 layout) ----------
__global__ void pack_w2_kernel(const float* __restrict__ w2) {
    int i = blockIdx.x * blockDim.x + threadIdx.x;
    if (i >= 160 * 72) return;
    int r = i / 72, nn = i - r * 72;
    uint32_t v = (nn < 64) ? f2tf32(w2[nn * 160 + r]) : 0u;
    ((uint32_t*)g_w2t)[r * 72 + nn] = v;
}

// ---------------- Stage A: persistent conv + fused gat_pre1 (R13) ---------
#define H1W   264
#define W2P   72
#define S_H1_OFF  0
#define S_W2_OFF  (32 * H1W)                  // 8448
#define S_IN_OFF  (S_W2_OFF + 160 * W2P)      // 19968
#define S_W1_OFF  (S_IN_OFF + 2 * 208)        // 20384
#define S_RED_OFF (S_W1_OFF + 320)            // 20704
#define S_H0_OFF  (S_RED_OFF + 512)           // 21216
#define S_PT_OFF  (S_H0_OFF + 64)             // 21280
#define CONV_SMEM_FLOATS (S_PT_OFF + 256)     // 21536
#define CONV_SMEM_BYTES  (CONV_SMEM_FLOATS * 4)

__global__ void __launch_bounds__(256, 2)
conv_fused_kernel(const float* __restrict__ x,
                  const float* __restrict__ w1, const float* __restrict__ b1,
                  const float* __restrict__ b2,
                  const float* __restrict__ W1, const float* __restrict__ a1,
                  float* __restrict__ Wh, float* __restrict__ f1, float* __restrict__ f2)
{
    extern __shared__ float sm[];
    float* s_h1  = sm + S_H1_OFF;
    float* s_w2  = sm + S_W2_OFF;
    float* s_in  = sm + S_IN_OFF;
    float* s_w1  = sm + S_W1_OFF;
    float* s_red = sm + S_RED_OFF;
    float* s_h0  = sm + S_H0_OFF;
    float* s_pt  = sm + S_PT_OFF;

    const int tid = threadIdx.x;

    for (int i = tid; i < 320; i += 256) s_w1[i] = w1[i];
    {
        uint4* dst = (uint4*)s_w2;
        for (int i = tid; i < 2880; i += 256) dst[i] = g_w2t[i];
    }
    if (tid < 16) {
        int c = tid >> 3, q = tid & 7;
        int idx = (q < 2) ? q : (200 + q);
        s_in[c * 208 + idx] = 0.f;
    }

    const int warp = tid >> 5;
    const int lane = tid & 31;
    const int g    = lane >> 2;
    const int t4   = lane & 3;

    const int sA = tid >> 1,          cA = tid & 1;
    const int sB = (tid + 256) >> 1,  cB = tid & 1;
    const bool has2 = (tid < 144);

    float xv0 = 0.f, xv1 = 0.f;
    {
        const int bn0 = blockIdx.x;
        const int b0  = bn0 >> 9;
        const int n0  = bn0 & 511;
        const float* xb = x + (size_t)b0 * SEQ * (NNODES * 2) + 2 * n0;
        xv0 = xb[(size_t)sA * (NNODES * 2) + cA];
        if (has2) xv1 = xb[(size_t)sB * (NNODES * 2) + cB];
    }

    for (int bn = blockIdx.x; bn < BATCH * NNODES; bn += CONV_GRID) {
        s_in[cA * 208 + 2 + sA] = xv0;
        if (has2) s_in[cB * 208 + 2 + sB] = xv1;
        __syncthreads();

        {
            const int ic = tid >> 3;
            const int j  = tid & 7;
            const int sj = 25 * j;
            const float b1i = b1[ic];
            const float* w  = s_w1 + ic * 10;
            uint32_t* h1u = (uint32_t*)(s_h1 + ic * H1W);

            float a0[29], a1v[29];
            const float* i0 = s_in + sj;
            const float* i1 = s_in + 208 + sj;
#pragma unroll
            for (int q = 0; q < 29; q++) { a0[q] = i0[q]; a1v[q] = i1[q]; }

#pragma unroll
            for (int q = 0; q < 25; q++) {
                float acc = b1i;
#pragma unroll
                for (int k = 0; k < 5; k++)
                    acc = fmaf(w[k], a0[q + k], fmaf(w[5 + k], a1v[q + k], acc));
                h1u[2 + sj + q] = f2tf32(fmaxf(acc, 0.f));
            }
            if (j == 0) { h1u[0] = 0u; h1u[1] = 0u; }
            if (j == 7) {
#pragma unroll
                for (int q = 0; q < 10; q++) h1u[202 + q] = 0u;
            }
        }
        __syncthreads();

        {
            const int bnn = bn + CONV_GRID;
            if (bnn < BATCH * NNODES) {
                const int bb = bnn >> 9;
                const int nn = bnn & 511;
                const float* xb = x + (size_t)bb * SEQ * (NNODES * 2) + 2 * nn;
                xv0 = xb[(size_t)sA * (NNODES * 2) + cA];
                if (has2) xv1 = xb[(size_t)sB * (NNODES * 2) + cB];
            }
        }

        const uint32_t* h1u = (const uint32_t*)s_h1;
        const uint32_t* w2u = (const uint32_t*)s_w2;

        float c[2][8][4];
#pragma unroll
        for (int mt = 0; mt < 2; mt++)
#pragma unroll
            for (int nt = 0; nt < 8; nt++)
#pragma unroll
                for (int q = 0; q < 4; q++) c[mt][nt][q] = 0.f;

#pragma unroll 2
        for (int kc = 0; kc < 20; kc++) {
            const int r0 = kc * 8 + t4;
            const int r1 = r0 + 4;
            const int ic0 = r0 / 5, k0 = r0 - ic0 * 5;
            const int ic1 = r1 / 5, k1 = r1 - ic1 * 5;

            uint32_t bb0[8], bb1[8];
#pragma unroll
            for (int nt = 0; nt < 8; nt++) {
                bb0[nt] = w2u[r0 * W2P + nt * 8 + g];
                bb1[nt] = w2u[r1 * W2P + nt * 8 + g];
            }

            const int ao0 = ic0 * H1W + k0;
            const int ao1 = ic1 * H1W + k1;
#pragma unroll
            for (int mt = 0; mt < 2; mt++) {
                const int tile = warp + 8 * mt;
                if (tile >= 13) continue;
                const int sb = tile * 16 + g;
                uint32_t a0 = h1u[ao0 + sb];
                uint32_t a1 = h1u[ao0 + sb + 8];
                uint32_t a2 = h1u[ao1 + sb];
                uint32_t a3 = h1u[ao1 + sb + 8];
#pragma unroll
                for (int nt = 0; nt < 8; nt++)
                    mma_tf32(c[mt][nt], a0, a1, a2, a3, bb0[nt], bb1[nt]);
            }
        }

#pragma unroll
        for (int nt = 0; nt < 8; nt++) {
            const int n0 = nt * 8 + 2 * t4;
            const float bias0 = b2[n0], bias1 = b2[n0 + 1];
            float sm0 = 0.f, sm1 = 0.f;
#pragma unroll
            for (int mt = 0; mt < 2; mt++) {
                const int tile = warp + 8 * mt;
                if (tile >= 13) continue;
                const int rA = tile * 16 + g;
                const int rB = rA + 8;
                if (rA < 200) {
                    sm0 += fmaxf(c[mt][nt][0] + bias0, 0.f);
                    sm1 += fmaxf(c[mt][nt][1] + bias1, 0.f);
                }
                if (rB < 200) {
                    sm0 += fmaxf(c[mt][nt][2] + bias0, 0.f);
                    sm1 += fmaxf(c[mt][nt][3] + bias1, 0.f);
                }
            }
#pragma unroll
            for (int off = 16; off >= 4; off >>= 1) {
                sm0 += __shfl_down_sync(0xffffffffu, sm0, off);
                sm1 += __shfl_down_sync(0xffffffffu, sm1, off);
            }
            if (lane < 4) {
                s_red[warp * 64 + nt * 8 + 2 * lane]     = sm0;
                s_red[warp * 64 + nt * 8 + 2 * lane + 1] = sm1;
            }
        }
        __syncthreads();

        if (tid < 64) {
            float t = 0.f;
#pragma unroll
            for (int w = 0; w < 8; w++) t += s_red[w * 64 + tid];
            s_h0[tid] = t * (1.f / 200.f);
        }
        __syncthreads();

        // fused gat_pre1
        {
            const int kq = tid >> 6;
            const int d  = tid & 63;
            float acc = 0.f;
#pragma unroll
            for (int i = 0; i < 16; i++) {
                int k = kq * 16 + i;
                acc = fmaf(s_h0[k], __ldg(W1 + k * 64 + d), acc);
            }
            s_pt[kq * 64 + d] = acc;
        }
        __syncthreads();

        if (tid < 64) {
            float wh = s_pt[tid] + s_pt[64 + tid] + s_pt[128 + tid] + s_pt[192 + tid];
            Wh[(size_t)bn * 64 + tid] = tf32v(wh);   // store tf32-rounded for MMA B use
            float v1 = wh * __ldg(a1 + tid);
            float v2 = wh * __ldg(a1 + 64 + tid);
#pragma unroll
            for (int o = 16; o; o >>= 1) {
                v1 += __shfl_down_sync(0xffffffffu, v1, o);
                v2 += __shfl_down_sync(0xffffffffu, v2, o);
            }
            if ((tid & 31) == 0) {
                s_pt[(tid >> 5) * 2]     = v1;
                s_pt[(tid >> 5) * 2 + 1] = v2;
            }
        }
        __syncthreads();
        if (tid == 0) {
            f1[bn] = s_pt[0] + s_pt[2];
            f2[bn] = s_pt[1] + s_pt[3];
        }
        __syncthreads();
    }
}

// ---------------- attention smem layout (tf32-MMA version) ----
// sp    [16][516]  tf32 p values      : 0     .. 8256
// sWh   [64][72]   tf32 Wh/W2 tile    : 8256  .. 12864
// s_f2  [512]                          : 12864 .. 13376
// s_hl  [16][68]   tf32 h1 (att1)      : 13376 .. 14464
// ssum  [16]                           : 14464 .. 14480
// s_part[8][16][2]                     : 14480 .. 14736
#define A_SP   0
#define A_SPW  516
#define A_SWH  8256
#define A_F2   12864
#define A_HL   13376
#define A_HLW  68
#define A_SUM  14464
#define A_PART 14480
#define ATT_SMEM_FLOATS 14736
#define ATT_SMEM_BYTES  (ATT_SMEM_FLOATS * 4)

// phase A: 8 warps x 2 rows; p stored tf32-rounded; lsum from rounded values
__device__ __forceinline__ void att_softmax_phase(
    float* sp, float* s_f2, float* ssum,
    const float* __restrict__ f1, const float* __restrict__ f2,
    const int* __restrict__ adj, int b, int i0, int tid)
{
    const int w  = tid >> 5;
    const int ln = tid & 31;

    for (int i = tid; i < 512; i += 256) s_f2[i] = f2[b * NNODES + i];
    __syncthreads();

#pragma unroll
    for (int rr = 0; rr < 2; rr++) {
        const int r = w * 2 + rr;
        const int i = i0 + r;
        const float f1i = f1[b * NNODES + i];
        const int4* adj4 = (const int4*)(adj + (size_t)i * NNODES);
        const float4* f2q = (const float4*)s_f2;

        float ev[16];
        float lmax = -3.4e38f;
#pragma unroll
        for (int t = 0; t < 4; t++) {
            int q = ln + 32 * t;
            int4 am = adj4[q];
            float4 fv = f2q[q];
            float e0 = f1i + fv.x; e0 = (e0 > 0.f) ? e0 : ALPHA * e0; e0 = (am.x > 0) ? e0 : NEGBIG;
            float e1 = f1i + fv.y; e1 = (e1 > 0.f) ? e1 : ALPHA * e1; e1 = (am.y > 0) ? e1 : NEGBIG;
            float e2 = f1i + fv.z; e2 = (e2 > 0.f) ? e2 : ALPHA * e2; e2 = (am.z > 0) ? e2 : NEGBIG;
            float e3 = f1i + fv.w; e3 = (e3 > 0.f) ? e3 : ALPHA * e3; e3 = (am.w > 0) ? e3 : NEGBIG;
            ev[4 * t]     = e0; ev[4 * t + 1] = e1;
            ev[4 * t + 2] = e2; ev[4 * t + 3] = e3;
            lmax = fmaxf(lmax, fmaxf(fmaxf(e0, e1), fmaxf(e2, e3)));
        }
#pragma unroll
        for (int o = 16; o; o >>= 1)
            lmax = fmaxf(lmax, __shfl_xor_sync(0xffffffffu, lmax, o));

        float lsum = 0.f;
        float4* spr = (float4*)(sp + r * A_SPW);
#pragma unroll
        for (int t = 0; t < 4; t++) {
            int q = ln + 32 * t;
            float4 pv;
            pv.x = tf32v(__expf(ev[4 * t]     - lmax));
            pv.y = tf32v(__expf(ev[4 * t + 1] - lmax));
            pv.z = tf32v(__expf(ev[4 * t + 2] - lmax));
            pv.w = tf32v(__expf(ev[4 * t + 3] - lmax));
            spr[q] = pv;
            lsum += pv.x + pv.y + pv.z + pv.w;
        }
#pragma unroll
        for (int o = 16; o; o >>= 1)
            lsum += __shfl_xor_sync(0xffffffffu, lsum, o);
        if (ln == 0) ssum[r] = lsum;
    }
    __syncthreads();
}

// phase B (MMA): D[16][64] = p[16][512] @ Wh[512][64]; warp w owns n-tile w.
// c: c0=D[g][2t4], c1=D[g][2t4+1], c2=D[g+8][2t4], c3=D[g+8][2t4+1]
__device__ __forceinline__ void att_agg_mma(
    const float* sp, float* sWh, const float* __restrict__ Whb,
    int w, int g, int t4, int tid, float* c)
{
    c[0] = c[1] = c[2] = c[3] = 0.f;
    const uint32_t* spu = (const uint32_t*)sp;
    const uint32_t* swu = (const uint32_t*)sWh;

    float buf[16];
#pragma unroll
    for (int t = 0; t < 16; t++) {
        int idx = tid + t * 256;
        buf[t] = Whb[(size_t)(idx >> 6) * 64 + (idx & 63)];
    }

    for (int jt = 0; jt < 8; jt++) {
#pragma unroll
        for (int t = 0; t < 16; t++) {
            int idx = tid + t * 256;
            sWh[(idx >> 6) * 72 + (idx & 63)] = buf[t];
        }
        __syncthreads();
        if (jt < 7) {
#pragma unroll
            for (int t = 0; t < 16; t++) {
                int idx = tid + t * 256;
                buf[t] = Whb[(size_t)((jt + 1) * 64 + (idx >> 6)) * 64 + (idx & 63)];
            }
        }
#pragma unroll
        for (int kk = 0; kk < 8; kk++) {
            const int ka = jt * 64 + kk * 8 + t4;
            uint32_t a0 = spu[g * A_SPW + ka];
            uint32_t a1 = spu[(g + 8) * A_SPW + ka];
            uint32_t a2 = spu[g * A_SPW + ka + 4];
            uint32_t a3 = spu[(g + 8) * A_SPW + ka + 4];
            uint32_t b0 = swu[(kk * 8 + t4) * 72 + w * 8 + g];
            uint32_t b1 = swu[(kk * 8 + t4 + 4) * 72 + w * 8 + g];
            mma_tf32(c, a0, a1, a2, a3, b0, b1);
        }
        __syncthreads();
    }
}

// ---------------- Stage B: attention layer1 + fused gat_pre2 (MMA) --------
__global__ void __launch_bounds__(256)
gat_att1_kernel(const float* __restrict__ Wh, const float* __restrict__ f1,
                const float* __restrict__ f2, const int* __restrict__ adj,
                const float* __restrict__ W2, const float* __restrict__ a2,
                float* __restrict__ Wh2, float* __restrict__ f1o, float* __restrict__ f2o)
{
    extern __shared__ float dsm[];
    float* sp     = dsm + A_SP;
    float* sWh    = dsm + A_SWH;
    float* s_f2   = dsm + A_F2;
    float* s_hl   = dsm + A_HL;
    float* ssum   = dsm + A_SUM;
    float* s_part = dsm + A_PART;

    const int blk = blockIdx.x;
    const int b   = blk >> 5;
    const int i0  = (blk & 31) * 16;
    const int tid = threadIdx.x;
    const int w   = tid >> 5;
    const int ln  = tid & 31;
    const int g   = ln >> 2;
    const int t4  = ln & 3;

    att_softmax_phase(sp, s_f2, ssum, f1, f2, adj, b, i0, tid);

    float c[4];
    att_agg_mma(sp, sWh, Wh + (size_t)b * NNODES * HID, w, g, t4, tid, c);

    // h1 = relu(c / ssum) -> s_hl tf32 (stride 68)
    {
        uint32_t* hlu = (uint32_t*)s_hl;
        const float inv0 = 1.f / ssum[g];
        const float inv1 = 1.f / ssum[g + 8];
        const int col = w * 8 + 2 * t4;
        hlu[g * A_HLW + col]           = f2tf32(fmaxf(c[0] * inv0, 0.f));
        hlu[g * A_HLW + col + 1]       = f2tf32(fmaxf(c[1] * inv0, 0.f));
        hlu[(g + 8) * A_HLW + col]     = f2tf32(fmaxf(c[2] * inv1, 0.f));
        hlu[(g + 8) * A_HLW + col + 1] = f2tf32(fmaxf(c[3] * inv1, 0.f));
    }
    // W2 -> sWh tf32 (stride 72)
#pragma unroll
    for (int t = 0; t < 16; t++) {
        int idx = tid + t * 256;
        ((uint32_t*)sWh)[(idx >> 6) * 72 + (idx & 63)] = f2tf32(W2[idx]);
    }
    __syncthreads();

    // pre2 MMA: Wh2[16][64] = h1 @ W2; warp w owns n-tile w
    float cc[4] = {0.f, 0.f, 0.f, 0.f};
    {
        const uint32_t* hlu = (const uint32_t*)s_hl;
        const uint32_t* swu = (const uint32_t*)sWh;
#pragma unroll
        for (int kk = 0; kk < 8; kk++) {
            const int ka = kk * 8 + t4;
            uint32_t a0 = hlu[g * A_HLW + ka];
            uint32_t a1 = hlu[(g + 8) * A_HLW + ka];
            uint32_t a2 = hlu[g * A_HLW + ka + 4];
            uint32_t a3 = hlu[(g + 8) * A_HLW + ka + 4];
            uint32_t b0 = swu[ka * 72 + w * 8 + g];
            uint32_t b1 = swu[(ka + 4) * 72 + w * 8 + g];
            mma_tf32(cc, a0, a1, a2, a3, b0, b1);
        }
    }

    // Wh2 store (tf32-rounded) + f1o/f2o
    {
        const int col  = w * 8 + 2 * t4;
        const int rowA = b * NNODES + i0 + g;
        const int rowB = rowA + 8;
        ((float2*)(Wh2 + (size_t)rowA * 64 + col))[0] =
            make_float2(tf32v(cc[0]), tf32v(cc[1]));
        ((float2*)(Wh2 + (size_t)rowB * 64 + col))[0] =
            make_float2(tf32v(cc[2]), tf32v(cc[3]));

        const float ax = __ldg(a2 + col),      ay = __ldg(a2 + col + 1);
        const float bx = __ldg(a2 + 64 + col), by = __ldg(a2 + 64 + col + 1);
        float u0 = cc[0] * ax + cc[1] * ay;   // row g
        float v0 = cc[0] * bx + cc[1] * by;
        float u1 = cc[2] * ax + cc[3] * ay;   // row g+8
        float v1 = cc[2] * bx + cc[3] * by;
        // reduce across t4 within each quad
#pragma unroll
        for (int o = 2; o; o >>= 1) {
            u0 += __shfl_down_sync(0xffffffffu, u0, o, 4);
            v0 += __shfl_down_sync(0xffffffffu, v0, o, 4);
            u1 += __shfl_down_sync(0xffffffffu, u1, o, 4);
            v1 += __shfl_down_sync(0xffffffffu, v1, o, 4);
        }
        if (t4 == 0) {
            s_part[(w * 16 + g) * 2]           = u0;
            s_part[(w * 16 + g) * 2 + 1]       = v0;
            s_part[(w * 16 + g + 8) * 2]       = u1;
            s_part[(w * 16 + g + 8) * 2 + 1]   = v1;
        }
    }
    __syncthreads();
    if (tid < 32) {
        const int r = tid >> 1, which = tid & 1;
        float t = 0.f;
#pragma unroll
        for (int ww = 0; ww < 8; ww++) t += s_part[(ww * 16 + r) * 2 + which];
        if (which == 0) f1o[b * NNODES + i0 + r] = t;
        else            f2o[b * NNODES + i0 + r] = t;
    }
}

// ---------------- Stage C: attention layer2 (MMA) ----------
__global__ void __launch_bounds__(256)
gat_att2_kernel(const float* __restrict__ Wh, const float* __restrict__ f1,
                const float* __restrict__ f2, const int* __restrict__ adj,
                float* __restrict__ out)
{
    extern __shared__ float dsm[];
    float* sp   = dsm + A_SP;
    float* sWh  = dsm + A_SWH;
    float* s_f2 = dsm + A_F2;
    float* ssum = dsm + A_SUM;

    const int blk = blockIdx.x;
    const int b   = blk >> 5;
    const int i0  = (blk & 31) * 16;
    const int tid = threadIdx.x;
    const int w   = tid >> 5;
    const int ln  = tid & 31;
    const int g   = ln >> 2;
    const int t4  = ln & 3;

    att_softmax_phase(sp, s_f2, ssum, f1, f2, adj, b, i0, tid);

    float c[4];
    att_agg_mma(sp, sWh, Wh + (size_t)b * NNODES * HID, w, g, t4, tid, c);

    const float inv0 = 1.f / ssum[g];
    const float inv1 = 1.f / ssum[g + 8];
    const int col  = w * 8 + 2 * t4;
    const int rowA = b * NNODES + i0 + g;
    const int rowB = rowA + 8;
    ((float2*)(out + (size_t)rowA * 64 + col))[0] = make_float2(c[0] * inv0, c[1] * inv0);
    ((float2*)(out + (size_t)rowB * 64 + col))[0] = make_float2(c[2] * inv1, c[3] * inv1);
}

// ---------------- Stage D: edge MLP (16 edges/block, smem weights) --------
#define EPB 16
__global__ void __launch_bounds__(1024)
edge_mlp_kernel(const float* __restrict__ h, const int* __restrict__ eidx,
                const float* __restrict__ fc1w, const float* __restrict__ fc1b,
                const float* __restrict__ fc2w, const float* __restrict__ fc2b,
                float* __restrict__ out)
{
    __shared__ float sw[128 * 64];
    __shared__ float she[EPB][128];
    __shared__ float sr[EPB][2];

    const int tid = threadIdx.x;
    const int b   = blockIdx.y;

    for (int i = tid; i < 128 * 64; i += 1024) sw[i] = fc1w[i];

    const int es = tid >> 6;
    const int t  = tid & 63;
    const int e  = blockIdx.x * EPB + es;

    const int i1 = eidx[2 * e];
    const int i2 = eidx[2 * e + 1];
    she[es][t]      = h[((size_t)b * NNODES + i1) * HID + t];
    she[es][64 + t] = h[((size_t)b * NNODES + i2) * HID + t];
    __syncthreads();

    float acc = fc1b[t];
    const float* sher = she[es];
#pragma unroll 8
    for (int k = 0; k < 128; k++)
        acc = fmaf(sher[k], sw[k * 64 + t], acc);
    acc = fmaxf(acc, 0.f);

    float v = acc * fc2w[t];
#pragma unroll
    for (int o = 16; o; o >>= 1)
        v += __shfl_down_sync(0xffffffffu, v, o);
    if ((t & 31) == 0) sr[es][t >> 5] = v;
    __syncthreads();
    if (t == 0) {
        float z = sr[es][0] + sr[es][1] + fc2b[0];
        out[(size_t)b * NEDGES + e] = 1.f / (1.f + expf(-z));
    }
}

// ---------------- launch ----------------
extern "C" void kernel_launch(void* const* d_in, const int* in_sizes, int n_in,
                              void* d_out, int out_size)
{
    const float* x    = (const float*)d_in[0];
    const int*   adj  = (const int*)  d_in[1];
    const int*   eidx = (const int*)  d_in[2];
    const float* w1   = (const float*)d_in[3];
    const float* b1   = (const float*)d_in[4];
    const float* w2   = (const float*)d_in[5];
    const float* b2   = (const float*)d_in[6];
    const float* W1   = (const float*)d_in[7];
    const float* a1   = (const float*)d_in[8];
    const float* W2   = (const float*)d_in[9];
    const float* a2   = (const float*)d_in[10];
    const float* fc1w = (const float*)d_in[11];
    const float* fc1b = (const float*)d_in[12];
    const float* fc2w = (const float*)d_in[13];
    const float* fc2b = (const float*)d_in[14];
    float* out = (float*)d_out;

    float *Wh1, *Wh2, *h2, *f1a, *f2a, *f1b, *f2b;
    cudaGetSymbolAddress((void**)&Wh1, g_Wh1);
    cudaGetSymbolAddress((void**)&Wh2, g_Wh2);
    cudaGetSymbolAddress((void**)&h2,  g_h2);
    cudaGetSymbolAddress((void**)&f1a, g_f1a);
    cudaGetSymbolAddress((void**)&f2a, g_f2a);
    cudaGetSymbolAddress((void**)&f1b, g_f1b);
    cudaGetSymbolAddress((void**)&f2b, g_f2b);

    cudaFuncSetAttribute(conv_fused_kernel,
                         cudaFuncAttributeMaxDynamicSharedMemorySize,
                         CONV_SMEM_BYTES);
    cudaFuncSetAttribute(gat_att1_kernel,
                         cudaFuncAttributeMaxDynamicSharedMemorySize,
                         ATT_SMEM_BYTES);
    cudaFuncSetAttribute(gat_att2_kernel,
                         cudaFuncAttributeMaxDynamicSharedMemorySize,
                         ATT_SMEM_BYTES);

    pack_w2_kernel<<<(160 * 72 + 255) / 256, 256>>>(w2);

    // Stage A: persistent conv with pipelined input prefetch (R13)
    conv_fused_kernel<<<CONV_GRID, 256, CONV_SMEM_BYTES>>>(
        x, w1, b1, b2, W1, a1, Wh1, f1a, f2a);

    gat_att1_kernel<<<(BATCH * NNODES) / 16, 256, ATT_SMEM_BYTES>>>(
        Wh1, f1a, f2a, adj, W2, a2, Wh2, f1b, f2b);

    gat_att2_kernel<<<(BATCH * NNODES) / 16, 256, ATT_SMEM_BYTES>>>(
        Wh2, f1b, f2b, adj, h2);

    dim3 eg(NEDGES / EPB, BATCH);
    edge_mlp_kernel<<<eg, 1024>>>(h2, eidx, fc1w, fc1b, fc2w, fc2b, out);
}